// round 4
// baseline (speedup 1.0000x reference)
#include <cuda_runtime.h>
#include <cuda_bf16.h>
#include <stdint.h>

// HSTUBlockPostprocessor: jagged gather of candidate rows + row-wise L2 norm.
//
// Inputs: values f32 [L,512]; seqlen_offsets i32 [B+1]; num_candidates_offsets
// i32 [B+1]; total_candidates i32 [1].
// Output: emb [total_candidates,512] f32 (+ fused tail: seqlen B floats,
// nc_offsets B+1 floats).
//
// src_row = seqlen_offsets[seg+1] - nc[seg+1] + idx,  nc[seg] <= idx < nc[seg+1].
//
// R4: replace evict-first (__ldcs/__stcs) with evict-normal L2 caching
// (__ldcg/__stcg). Steady-state working set (64MB re-read + 64MB re-written
// per graph replay) nearly fits the 126MB L2; evict-first was actively
// flushing the reuse. L1 is bypassed (flushed per launch anyway).

#define D_DIM 512
#define WARPS_PER_BLOCK 8
#define ROWS_PER_WARP 2
#define ROWS_PER_BLOCK (WARPS_PER_BLOCK * ROWS_PER_WARP)
#define THREADS_PER_BLOCK (WARPS_PER_BLOCK * 32)

__global__ __launch_bounds__(THREADS_PER_BLOCK)
void hstu_gather_l2norm_kernel(const float* __restrict__ values,
                               const int* __restrict__ seqlen_offsets,
                               const int* __restrict__ nc_offsets,
                               float* __restrict__ out,
                               int n_rows, int n_seg,
                               float* __restrict__ out_tail) {
    // ── Fused tail write (block 0 only; ~257 elements) ──
    if (out_tail != nullptr && blockIdx.x == 0) {
        for (int i = threadIdx.x; i <= n_seg; i += THREADS_PER_BLOCK) {
            int nc_i = __ldg(&nc_offsets[i]);
            if (i < n_seg)
                out_tail[i] = (float)(__ldg(&nc_offsets[i + 1]) - nc_i);
            out_tail[n_seg + i] = (float)nc_i;
        }
    }

    const int warp = blockIdx.x * WARPS_PER_BLOCK + (threadIdx.x >> 5);
    const int lane = threadIdx.x & 31;
    const int r0 = warp * ROWS_PER_WARP;
    if (r0 >= n_rows) return;
    const int r1 = r0 + 1;
    const bool have_r1 = (r1 < n_rows);

    // ── Warp-cooperative segment search (ballot over 32 monotone probes) ──
    int q = (int)(((long long)lane * n_seg) / 31);
    if (lane == 31) q = n_seg;
    const int ncq = __ldg(&nc_offsets[q]);
    const unsigned m0 = __ballot_sync(0xFFFFFFFFu, ncq <= r0);
    const unsigned m1 = __ballot_sync(0xFFFFFFFFu, ncq <= r1);
    const int c0 = __popc(m0);
    const int c1 = __popc(m1);
    const int qlo0 = __shfl_sync(0xFFFFFFFFu, q, c0 - 1);
    const int qhi0 = __shfl_sync(0xFFFFFFFFu, q, c0);
    const int qlo1 = __shfl_sync(0xFFFFFFFFu, q, c1 - 1);
    const int qhi1 = __shfl_sync(0xFFFFFFFFu, q, c1);

    int seg0 = qlo0, seg1 = qlo1;
    {
        const int gap0 = qhi0 - qlo0 - 1;
        const int gap1 = qhi1 - qlo1 - 1;
        bool p0 = false, p1 = false;
        if (lane < gap0)
            p0 = (__ldg(&nc_offsets[qlo0 + 1 + lane]) <= r0);
        if (lane < gap1)
            p1 = (__ldg(&nc_offsets[qlo1 + 1 + lane]) <= r1);
        seg0 += __popc(__ballot_sync(0xFFFFFFFFu, p0));
        seg1 += __popc(__ballot_sync(0xFFFFFFFFu, p1));
    }

    const long long src0 =
        (long long)(__ldg(&seqlen_offsets[seg0 + 1]) - __ldg(&nc_offsets[seg0 + 1])) + r0;
    const long long src1 =
        (long long)(__ldg(&seqlen_offsets[seg1 + 1]) - __ldg(&nc_offsets[seg1 + 1])) + r1;

    const float4* __restrict__ s0 =
        reinterpret_cast<const float4*>(values + src0 * (long long)D_DIM);
    const float4* __restrict__ s1 =
        reinterpret_cast<const float4*>(values + src1 * (long long)D_DIM);
    float4* __restrict__ d0 = reinterpret_cast<float4*>(out + (long long)r0 * D_DIM);
    float4* __restrict__ d1 = reinterpret_cast<float4*>(out + (long long)r1 * D_DIM);

    // 8 independent 128-bit loads per lane, L2 evict-normal (replay reuse).
    float4 a0 = __ldcg(&s0[lane]);
    float4 a1 = __ldcg(&s0[lane + 32]);
    float4 a2 = __ldcg(&s0[lane + 64]);
    float4 a3 = __ldcg(&s0[lane + 96]);
    float4 b0, b1, b2, b3;
    if (have_r1) {
        b0 = __ldcg(&s1[lane]);
        b1 = __ldcg(&s1[lane + 32]);
        b2 = __ldcg(&s1[lane + 64]);
        b3 = __ldcg(&s1[lane + 96]);
    } else {
        b0 = b1 = b2 = b3 = make_float4(0.f, 0.f, 0.f, 0.f);
    }

    float ss0 = a0.x * a0.x + a0.y * a0.y + a0.z * a0.z + a0.w * a0.w;
    ss0 += a1.x * a1.x + a1.y * a1.y + a1.z * a1.z + a1.w * a1.w;
    ss0 += a2.x * a2.x + a2.y * a2.y + a2.z * a2.z + a2.w * a2.w;
    ss0 += a3.x * a3.x + a3.y * a3.y + a3.z * a3.z + a3.w * a3.w;
    float ss1 = b0.x * b0.x + b0.y * b0.y + b0.z * b0.z + b0.w * b0.w;
    ss1 += b1.x * b1.x + b1.y * b1.y + b1.z * b1.z + b1.w * b1.w;
    ss1 += b2.x * b2.x + b2.y * b2.y + b2.z * b2.z + b2.w * b2.w;
    ss1 += b3.x * b3.x + b3.y * b3.y + b3.z * b3.z + b3.w * b3.w;

    #pragma unroll
    for (int off = 16; off > 0; off >>= 1) {
        ss0 += __shfl_xor_sync(0xFFFFFFFFu, ss0, off);
        ss1 += __shfl_xor_sync(0xFFFFFFFFu, ss1, off);
    }

    // 1/max(sqrt(ss),1e-6) == rsqrt(max(ss,1e-12)) (sqrt monotone).
    const float sc0 = rsqrtf(fmaxf(ss0, 1e-12f));
    const float sc1 = rsqrtf(fmaxf(ss1, 1e-12f));

    a0.x *= sc0; a0.y *= sc0; a0.z *= sc0; a0.w *= sc0;
    a1.x *= sc0; a1.y *= sc0; a1.z *= sc0; a1.w *= sc0;
    a2.x *= sc0; a2.y *= sc0; a2.z *= sc0; a2.w *= sc0;
    a3.x *= sc0; a3.y *= sc0; a3.z *= sc0; a3.w *= sc0;
    __stcg(&d0[lane],      a0);
    __stcg(&d0[lane + 32], a1);
    __stcg(&d0[lane + 64], a2);
    __stcg(&d0[lane + 96], a3);

    if (have_r1) {
        b0.x *= sc1; b0.y *= sc1; b0.z *= sc1; b0.w *= sc1;
        b1.x *= sc1; b1.y *= sc1; b1.z *= sc1; b1.w *= sc1;
        b2.x *= sc1; b2.y *= sc1; b2.z *= sc1; b2.w *= sc1;
        b3.x *= sc1; b3.y *= sc1; b3.z *= sc1; b3.w *= sc1;
        __stcg(&d1[lane],      b0);
        __stcg(&d1[lane + 32], b1);
        __stcg(&d1[lane + 64], b2);
        __stcg(&d1[lane + 96], b3);
    }
}

extern "C" void kernel_launch(void* const* d_in, const int* in_sizes, int n_in,
                              void* d_out, int out_size) {
    const float* values = (const float*)d_in[0];
    const int* seqlen_offsets = (const int*)d_in[1];
    const int* nc_offsets = (const int*)d_in[2];
    float* out = (float*)d_out;

    const int n_seg = in_sizes[2] - 1;  // B

    long long emb_elems = out_size;
    float* out_tail = nullptr;
    long long tail = 2LL * n_seg + 1;
    if ((long long)out_size % D_DIM != 0 &&
        ((long long)out_size - tail) % D_DIM == 0 && (long long)out_size > tail) {
        emb_elems = (long long)out_size - tail;
        out_tail = out + emb_elems;
    }
    const int n_rows = (int)(emb_elems / D_DIM);

    const int blocks = (n_rows + ROWS_PER_BLOCK - 1) / ROWS_PER_BLOCK;
    hstu_gather_l2norm_kernel<<<blocks, THREADS_PER_BLOCK>>>(
        values, seqlen_offsets, nc_offsets, out, n_rows, n_seg, out_tail);
}

// round 5
// speedup vs baseline: 1.0972x; 1.0972x over previous
#include <cuda_runtime.h>
#include <cuda_bf16.h>
#include <stdint.h>

// HSTUBlockPostprocessor: jagged gather of candidate rows + row-wise L2 norm.
//
// Inputs: values f32 [L,512]; seqlen_offsets i32 [B+1]; num_candidates_offsets
// i32 [B+1]; total_candidates i32 [1].
// Output: emb [total_candidates,512] f32 (+ fused tail: seqlen B floats,
// nc_offsets B+1 floats).
//
// src_row = seqlen_offsets[seg+1] - nc[seg+1] + idx,  nc[seg] <= idx < nc[seg+1].
//
// R5 cache policy (graph-replay steady state):
//   reads  -> __ldcs (evict-first: single-touch per replay, must not evict the
//             output stream from L2)
//   stores -> __stcg (evict-normal: output is rewritten every replay and never
//             read; if it stays dirty-resident in L2, steady-state DRAM write
//             traffic collapses to ~0)
// R4 showed ldcg+stcg thrash (25.3us); R2/3 ldcs+stcs forced full writeback
// (23.3us). This is the asymmetric combo matching the actual reuse pattern.

#define D_DIM 512
#define WARPS_PER_BLOCK 8
#define ROWS_PER_WARP 2
#define ROWS_PER_BLOCK (WARPS_PER_BLOCK * ROWS_PER_WARP)
#define THREADS_PER_BLOCK (WARPS_PER_BLOCK * 32)

__global__ __launch_bounds__(THREADS_PER_BLOCK)
void hstu_gather_l2norm_kernel(const float* __restrict__ values,
                               const int* __restrict__ seqlen_offsets,
                               const int* __restrict__ nc_offsets,
                               float* __restrict__ out,
                               int n_rows, int n_seg,
                               float* __restrict__ out_tail) {
    // ── Fused tail write (block 0 only; ~257 elements) ──
    if (out_tail != nullptr && blockIdx.x == 0) {
        for (int i = threadIdx.x; i <= n_seg; i += THREADS_PER_BLOCK) {
            int nc_i = __ldg(&nc_offsets[i]);
            if (i < n_seg)
                out_tail[i] = (float)(__ldg(&nc_offsets[i + 1]) - nc_i);
            out_tail[n_seg + i] = (float)nc_i;
        }
    }

    const int warp = blockIdx.x * WARPS_PER_BLOCK + (threadIdx.x >> 5);
    const int lane = threadIdx.x & 31;
    const int r0 = warp * ROWS_PER_WARP;
    if (r0 >= n_rows) return;
    const int r1 = r0 + 1;
    const bool have_r1 = (r1 < n_rows);

    // ── Warp-cooperative segment search (ballot over 32 monotone probes) ──
    int q = (int)(((long long)lane * n_seg) / 31);
    if (lane == 31) q = n_seg;
    const int ncq = __ldg(&nc_offsets[q]);
    const unsigned m0 = __ballot_sync(0xFFFFFFFFu, ncq <= r0);
    const unsigned m1 = __ballot_sync(0xFFFFFFFFu, ncq <= r1);
    const int c0 = __popc(m0);
    const int c1 = __popc(m1);
    const int qlo0 = __shfl_sync(0xFFFFFFFFu, q, c0 - 1);
    const int qhi0 = __shfl_sync(0xFFFFFFFFu, q, c0);
    const int qlo1 = __shfl_sync(0xFFFFFFFFu, q, c1 - 1);
    const int qhi1 = __shfl_sync(0xFFFFFFFFu, q, c1);

    int seg0 = qlo0, seg1 = qlo1;
    {
        const int gap0 = qhi0 - qlo0 - 1;
        const int gap1 = qhi1 - qlo1 - 1;
        bool p0 = false, p1 = false;
        if (lane < gap0)
            p0 = (__ldg(&nc_offsets[qlo0 + 1 + lane]) <= r0);
        if (lane < gap1)
            p1 = (__ldg(&nc_offsets[qlo1 + 1 + lane]) <= r1);
        seg0 += __popc(__ballot_sync(0xFFFFFFFFu, p0));
        seg1 += __popc(__ballot_sync(0xFFFFFFFFu, p1));
    }

    const long long src0 =
        (long long)(__ldg(&seqlen_offsets[seg0 + 1]) - __ldg(&nc_offsets[seg0 + 1])) + r0;
    const long long src1 =
        (long long)(__ldg(&seqlen_offsets[seg1 + 1]) - __ldg(&nc_offsets[seg1 + 1])) + r1;

    const float4* __restrict__ s0 =
        reinterpret_cast<const float4*>(values + src0 * (long long)D_DIM);
    const float4* __restrict__ s1 =
        reinterpret_cast<const float4*>(values + src1 * (long long)D_DIM);
    float4* __restrict__ d0 = reinterpret_cast<float4*>(out + (long long)r0 * D_DIM);
    float4* __restrict__ d1 = reinterpret_cast<float4*>(out + (long long)r1 * D_DIM);

    // 8 independent 128-bit evict-first loads per lane.
    float4 a0 = __ldcs(&s0[lane]);
    float4 a1 = __ldcs(&s0[lane + 32]);
    float4 a2 = __ldcs(&s0[lane + 64]);
    float4 a3 = __ldcs(&s0[lane + 96]);
    float4 b0, b1, b2, b3;
    if (have_r1) {
        b0 = __ldcs(&s1[lane]);
        b1 = __ldcs(&s1[lane + 32]);
        b2 = __ldcs(&s1[lane + 64]);
        b3 = __ldcs(&s1[lane + 96]);
    } else {
        b0 = b1 = b2 = b3 = make_float4(0.f, 0.f, 0.f, 0.f);
    }

    float ss0 = a0.x * a0.x + a0.y * a0.y + a0.z * a0.z + a0.w * a0.w;
    ss0 += a1.x * a1.x + a1.y * a1.y + a1.z * a1.z + a1.w * a1.w;
    ss0 += a2.x * a2.x + a2.y * a2.y + a2.z * a2.z + a2.w * a2.w;
    ss0 += a3.x * a3.x + a3.y * a3.y + a3.z * a3.z + a3.w * a3.w;
    float ss1 = b0.x * b0.x + b0.y * b0.y + b0.z * b0.z + b0.w * b0.w;
    ss1 += b1.x * b1.x + b1.y * b1.y + b1.z * b1.z + b1.w * b1.w;
    ss1 += b2.x * b2.x + b2.y * b2.y + b2.z * b2.z + b2.w * b2.w;
    ss1 += b3.x * b3.x + b3.y * b3.y + b3.z * b3.z + b3.w * b3.w;

    #pragma unroll
    for (int off = 16; off > 0; off >>= 1) {
        ss0 += __shfl_xor_sync(0xFFFFFFFFu, ss0, off);
        ss1 += __shfl_xor_sync(0xFFFFFFFFu, ss1, off);
    }

    // 1/max(sqrt(ss),1e-6) == rsqrt(max(ss,1e-12)) (sqrt monotone).
    const float sc0 = rsqrtf(fmaxf(ss0, 1e-12f));
    const float sc1 = rsqrtf(fmaxf(ss1, 1e-12f));

    a0.x *= sc0; a0.y *= sc0; a0.z *= sc0; a0.w *= sc0;
    a1.x *= sc0; a1.y *= sc0; a1.z *= sc0; a1.w *= sc0;
    a2.x *= sc0; a2.y *= sc0; a2.z *= sc0; a2.w *= sc0;
    a3.x *= sc0; a3.y *= sc0; a3.z *= sc0; a3.w *= sc0;
    __stcg(&d0[lane],      a0);
    __stcg(&d0[lane + 32], a1);
    __stcg(&d0[lane + 64], a2);
    __stcg(&d0[lane + 96], a3);

    if (have_r1) {
        b0.x *= sc1; b0.y *= sc1; b0.z *= sc1; b0.w *= sc1;
        b1.x *= sc1; b1.y *= sc1; b1.z *= sc1; b1.w *= sc1;
        b2.x *= sc1; b2.y *= sc1; b2.z *= sc1; b2.w *= sc1;
        b3.x *= sc1; b3.y *= sc1; b3.z *= sc1; b3.w *= sc1;
        __stcg(&d1[lane],      b0);
        __stcg(&d1[lane + 32], b1);
        __stcg(&d1[lane + 64], b2);
        __stcg(&d1[lane + 96], b3);
    }
}

extern "C" void kernel_launch(void* const* d_in, const int* in_sizes, int n_in,
                              void* d_out, int out_size) {
    const float* values = (const float*)d_in[0];
    const int* seqlen_offsets = (const int*)d_in[1];
    const int* nc_offsets = (const int*)d_in[2];
    float* out = (float*)d_out;

    const int n_seg = in_sizes[2] - 1;  // B

    long long emb_elems = out_size;
    float* out_tail = nullptr;
    long long tail = 2LL * n_seg + 1;
    if ((long long)out_size % D_DIM != 0 &&
        ((long long)out_size - tail) % D_DIM == 0 && (long long)out_size > tail) {
        emb_elems = (long long)out_size - tail;
        out_tail = out + emb_elems;
    }
    const int n_rows = (int)(emb_elems / D_DIM);

    const int blocks = (n_rows + ROWS_PER_BLOCK - 1) / ROWS_PER_BLOCK;
    hstu_gather_l2norm_kernel<<<blocks, THREADS_PER_BLOCK>>>(
        values, seqlen_offsets, nc_offsets, out, n_rows, n_seg, out_tail);
}

// round 6
// speedup vs baseline: 1.0987x; 1.0014x over previous
#include <cuda_runtime.h>
#include <cuda_bf16.h>
#include <stdint.h>

// HSTUBlockPostprocessor: jagged gather of candidate rows + row-wise L2 norm.
//
// Inputs: values f32 [L,512]; seqlen_offsets i32 [B+1]; num_candidates_offsets
// i32 [B+1]; total_candidates i32 [1].
// Output: emb [total_candidates,512] f32 (+ fused tail: seqlen, nc_offsets).
//
// src_row = seqlen_offsets[seg+1] - nc[seg+1] + idx,  nc[seg] <= idx < nc[seg+1].
//
// R6: persistent single-wave grid (608 blocks, 4/SM forced via launch_bounds)
// with a 2-stage software pipeline per warp: prefetch next row's loads before
// reducing/storing the current row. Eliminates the 2.3-wave quantization and
// the front-batched-LDG cross-CTA L1tex queue spike of the old one-shot grid.
// Cache policy (best of R2-R5 quadrant): reads __ldcs, stores __stcg.

#define D_DIM 512
#define WARPS_PER_BLOCK 8
#define THREADS_PER_BLOCK (WARPS_PER_BLOCK * 32)
#define GRID_BLOCKS 608   // 4 per SM x 152 SMs (GB300); grid-stride absorbs mismatch

__global__ __launch_bounds__(THREADS_PER_BLOCK, 4)
void hstu_gather_l2norm_kernel(const float* __restrict__ values,
                               const int* __restrict__ seqlen_offsets,
                               const int* __restrict__ nc_offsets,
                               float* __restrict__ out,
                               int n_rows, int n_seg,
                               float* __restrict__ out_tail) {
    // ── Fused tail write (block 0 only; ~257 elements) ──
    if (out_tail != nullptr && blockIdx.x == 0) {
        for (int i = threadIdx.x; i <= n_seg; i += THREADS_PER_BLOCK) {
            int nc_i = __ldg(&nc_offsets[i]);
            if (i < n_seg)
                out_tail[i] = (float)(__ldg(&nc_offsets[i + 1]) - nc_i);
            out_tail[n_seg + i] = (float)nc_i;
        }
    }

    const int lane = threadIdx.x & 31;
    const int gw = blockIdx.x * WARPS_PER_BLOCK + (threadIdx.x >> 5);
    const int nwarps = GRID_BLOCKS * WARPS_PER_BLOCK;

    // ── Loop-invariant level-1 probes for the ballot segment search ──
    int q = (int)(((long long)lane * n_seg) / 31);
    if (lane == 31) q = n_seg;
    const int ncq = __ldg(&nc_offsets[q]);

    // Warp-cooperative search: returns source float4* for candidate row r.
    auto find_src = [&](int r) -> const float4* {
        const unsigned m = __ballot_sync(0xFFFFFFFFu, ncq <= r);
        const int c = __popc(m);                       // in [1,31]
        const int qlo = __shfl_sync(0xFFFFFFFFu, q, c - 1);
        const int qhi = __shfl_sync(0xFFFFFFFFu, q, c);
        bool p = false;
        if (lane < qhi - qlo - 1)
            p = (__ldg(&nc_offsets[qlo + 1 + lane]) <= r);
        const int seg = qlo + __popc(__ballot_sync(0xFFFFFFFFu, p));
        const long long src =
            (long long)(__ldg(&seqlen_offsets[seg + 1]) - __ldg(&nc_offsets[seg + 1])) + r;
        return reinterpret_cast<const float4*>(values + src * (long long)D_DIM);
    };

    int row = gw;
    if (row >= n_rows) return;

    // Prologue: issue loads for the first row.
    const float4* sp = find_src(row);
    float4 c0 = __ldcs(&sp[lane]);
    float4 c1 = __ldcs(&sp[lane + 32]);
    float4 c2 = __ldcs(&sp[lane + 64]);
    float4 c3 = __ldcs(&sp[lane + 96]);

    while (true) {
        const int nrow = row + nwarps;
        const bool have_next = (nrow < n_rows);

        // Stage 2: prefetch next row before touching current row's data.
        float4 p0, p1, p2, p3;
        if (have_next) {
            const float4* np = find_src(nrow);
            p0 = __ldcs(&np[lane]);
            p1 = __ldcs(&np[lane + 32]);
            p2 = __ldcs(&np[lane + 64]);
            p3 = __ldcs(&np[lane + 96]);
        }

        // Reduce + normalize + store current row.
        float ss = c0.x * c0.x + c0.y * c0.y + c0.z * c0.z + c0.w * c0.w;
        ss += c1.x * c1.x + c1.y * c1.y + c1.z * c1.z + c1.w * c1.w;
        ss += c2.x * c2.x + c2.y * c2.y + c2.z * c2.z + c2.w * c2.w;
        ss += c3.x * c3.x + c3.y * c3.y + c3.z * c3.z + c3.w * c3.w;
        #pragma unroll
        for (int off = 16; off > 0; off >>= 1)
            ss += __shfl_xor_sync(0xFFFFFFFFu, ss, off);
        // 1/max(sqrt(ss),1e-6) == rsqrt(max(ss,1e-12)) (sqrt monotone).
        const float sc = rsqrtf(fmaxf(ss, 1e-12f));

        float4* dst = reinterpret_cast<float4*>(out + (long long)row * D_DIM);
        c0.x *= sc; c0.y *= sc; c0.z *= sc; c0.w *= sc;
        c1.x *= sc; c1.y *= sc; c1.z *= sc; c1.w *= sc;
        c2.x *= sc; c2.y *= sc; c2.z *= sc; c2.w *= sc;
        c3.x *= sc; c3.y *= sc; c3.z *= sc; c3.w *= sc;
        __stcg(&dst[lane],      c0);
        __stcg(&dst[lane + 32], c1);
        __stcg(&dst[lane + 64], c2);
        __stcg(&dst[lane + 96], c3);

        if (!have_next) break;
        row = nrow;
        c0 = p0; c1 = p1; c2 = p2; c3 = p3;
    }
}

extern "C" void kernel_launch(void* const* d_in, const int* in_sizes, int n_in,
                              void* d_out, int out_size) {
    const float* values = (const float*)d_in[0];
    const int* seqlen_offsets = (const int*)d_in[1];
    const int* nc_offsets = (const int*)d_in[2];
    float* out = (float*)d_out;

    const int n_seg = in_sizes[2] - 1;  // B

    long long emb_elems = out_size;
    float* out_tail = nullptr;
    long long tail = 2LL * n_seg + 1;
    if ((long long)out_size % D_DIM != 0 &&
        ((long long)out_size - tail) % D_DIM == 0 && (long long)out_size > tail) {
        emb_elems = (long long)out_size - tail;
        out_tail = out + emb_elems;
    }
    const int n_rows = (int)(emb_elems / D_DIM);

    hstu_gather_l2norm_kernel<<<GRID_BLOCKS, THREADS_PER_BLOCK>>>(
        values, seqlen_offsets, nc_offsets, out, n_rows, n_seg, out_tail);
}